// round 16
// baseline (speedup 1.0000x reference)
#include <cuda_runtime.h>
#include <cuda_fp16.h>

#define T_STEPS 1000
#define C_CH    3
#define H_DIM   64
#define W_DIM   64
#define HW      (H_DIM * W_DIM)       // 4096
#define HW4     (HW / 4)              // 1024
#define PIX     (C_CH * HW)           // 12288
#define PIX4    (PIX / 4)             // 3072
#define NSEG    50
#define SEGLEN  (T_STEPS / NSEG)      // 20
#define TILE_ROWS 16

__device__ __half g_E[(size_t)T_STEPS * PIX];     // ~24.5 MB scratch (fp16)
__device__ float  g_Psum[NSEG * PIX];             // ~2.5 MB
__device__ float  g_Ppre[NSEG * PIX];             // exclusive prefix of g_Psum
__constant__ float c_w[81];                       // conv weights (LDCU port)

// ---------------------------------------------------------------------------
// Kernel A (proven R7 body, fp16 E stores): 256 threads, one (16-row tile,
// image j). Thread = 1 row x 4 cols x 3 output channels (12 accumulators).
// ---------------------------------------------------------------------------
__global__ __launch_bounds__(256, 4) void conv_kernel(
    const float* __restrict__ src,       // images 0..T-1, (.., C, H, W)
    const float* __restrict__ temb,      // (T, 3)
    const int*   __restrict__ t_arr,     // (T,)
    const float* __restrict__ et_coeff)  // (T,)
{
    __shared__ float4 s_in4[3][18][18];  // [ci][row][quad]; quad q = cols 4q-4..4q-1

    const int j   = blockIdx.y;
    const int r0  = blockIdx.x * TILE_ROWS;
    const int tid = threadIdx.x;
    const int h   = tid >> 4;            // row 0..15
    const int k   = tid & 15;            // col-group 0..15 (cols 4k..4k+3)

    const float4* img4 = (const float4*)(src + (size_t)j * PIX);
    for (int l = tid; l < 3 * 18 * 18; l += 256) {
        int ci  = l / 324;
        int rem = l - ci * 324;
        int r   = rem / 18;
        int q   = rem - r * 18;
        int gh  = r0 + r - 1;
        float4 v = make_float4(0.f, 0.f, 0.f, 0.f);
        if (q >= 1 && q <= 16 && gh >= 0 && gh < H_DIM)
            v = img4[ci * HW4 + gh * 16 + (q - 1)];
        (&s_in4[0][0][0])[l] = v;
    }
    __syncthreads();

    const int   trev = __ldg(t_arr + j);
    const float ec   = __ldg(et_coeff + j);

    float acc[3][4];
#pragma unroll
    for (int c = 0; c < 3; c++) {
        const float tb = __ldg(temb + trev * 3 + c);
#pragma unroll
        for (int s = 0; s < 4; s++) acc[c][s] = tb;
    }

#pragma unroll 1
    for (int ci = 0; ci < 3; ci++) {
        float v[3][6];
#pragma unroll
        for (int r = 0; r < 3; r++) {
            float4 A = s_in4[ci][h + r][k];
            float4 B = s_in4[ci][h + r][k + 1];
            float4 C = s_in4[ci][h + r][k + 2];
            v[r][0] = A.w; v[r][1] = B.x; v[r][2] = B.y;
            v[r][3] = B.z; v[r][4] = B.w; v[r][5] = C.x;
        }
#pragma unroll
        for (int dh = 0; dh < 3; dh++)
#pragma unroll
            for (int dw = 0; dw < 3; dw++) {
                const int tap = ci * 9 + dh * 3 + dw;
                const float w0 = c_w[tap];
                const float w1 = c_w[27 + tap];
                const float w2 = c_w[54 + tap];
#pragma unroll
                for (int s = 0; s < 4; s++) {
                    const float xv = v[dh][dw + s];
                    acc[0][s] = fmaf(w0, xv, acc[0][s]);
                    acc[1][s] = fmaf(w1, xv, acc[1][s]);
                    acc[2][s] = fmaf(w2, xv, acc[2][s]);
                }
            }
    }

    __half* Ej = g_E + (size_t)j * PIX;
    const int gq = (r0 + h) * 16 + k;            // float4-group index in channel plane
#pragma unroll
    for (int c = 0; c < 3; c++) {
        union { uint2 u; __half2 h[2]; } pk;
        pk.h[0] = __floats2half2_rn(acc[c][0] * ec, acc[c][1] * ec);
        pk.h[1] = __floats2half2_rn(acc[c][2] * ec, acc[c][3] * ec);
        *(uint2*)(Ej + c * HW + gq * 4) = pk.u;  // STG.64
    }
}

// ---------------------------------------------------------------------------
// Kernel B: per-segment partial sums of E (fp16 loads, fp32 accumulate).
// 128-thread blocks for higher schedulable block count.
// ---------------------------------------------------------------------------
__global__ __launch_bounds__(128) void psum_kernel()
{
    const int p4  = blockIdx.x * 128 + threadIdx.x;   // < PIX4
    const int seg = blockIdx.y;
    const __half* base = g_E + (size_t)seg * SEGLEN * PIX + p4 * 4;
    float4 s = make_float4(0.f, 0.f, 0.f, 0.f);
#pragma unroll
    for (int j = 0; j < SEGLEN; j++) {
        uint2 u = *(const uint2*)(base + (size_t)j * PIX);
        float2 f0 = __half22float2(*(const __half2*)&u.x);
        float2 f1 = __half22float2(*(const __half2*)&u.y);
        s.x += f0.x; s.y += f0.y; s.z += f1.x; s.w += f1.y;
    }
    ((float4*)g_Psum)[seg * PIX4 + p4] = s;
}

// ---------------------------------------------------------------------------
// Kernel B2: exclusive prefix of g_Psum along segments (per scalar pixel).
// ---------------------------------------------------------------------------
__global__ __launch_bounds__(256) void prefix_kernel()
{
    const int p = blockIdx.x * 256 + threadIdx.x;     // < PIX
    float run = 0.f;
#pragma unroll 10
    for (int s = 0; s < NSEG; s++) {
        const float v = g_Psum[s * PIX + p];
        g_Ppre[s * PIX + p] = run;
        run += v;
    }
}

// ---------------------------------------------------------------------------
// Kernel C: offset (one load) + local scan + combine (fp16 E, fp32 math).
// 128-thread blocks -> 1200 schedulable blocks (latency-bound fix).
// ---------------------------------------------------------------------------
__global__ __launch_bounds__(128) void scan_combine_kernel(
    float*       __restrict__ dst,          // (T+1, C, H, W)
    const float* __restrict__ xT,           // first image of original x
    const float* __restrict__ alpha_ratio,  // (T,)
    const float* __restrict__ epc)          // (T,)
{
    const int seg = blockIdx.y;
    const int p4  = blockIdx.x * 128 + threadIdx.x;   // < PIX4

    float4 acc = ((const float4*)g_Ppre)[seg * PIX4 + p4];

    const float4 xv = ((const float4*)xT)[p4];
    if (seg == 0)
        ((float4*)dst)[p4] = xv;             // image 0 stays xT

    const int t0 = seg * SEGLEN;
    const __half* base = g_E + (size_t)t0 * PIX + p4 * 4;
#pragma unroll 10
    for (int jj = 0; jj < SEGLEN; jj++) {
        const int j = t0 + jj;
        uint2 u = __ldcs((const uint2*)(base + (size_t)jj * PIX));
        float2 f0 = __half22float2(*(const __half2*)&u.x);
        float2 f1 = __half22float2(*(const __half2*)&u.y);
        acc.x += f0.x; acc.y += f0.y; acc.z += f1.x; acc.w += f1.y;
        const float ar = __ldg(alpha_ratio + j);
        const float ep = __ldg(epc + j);
        float4 o;
        o.x = fmaf(ar, xv.x, ep * acc.x);
        o.y = fmaf(ar, xv.y, ep * acc.y);
        o.z = fmaf(ar, xv.z, ep * acc.z);
        o.w = fmaf(ar, xv.w, ep * acc.w);
        ((float4*)dst)[(size_t)(j + 1) * PIX4 + p4] = o;
    }
}

extern "C" void kernel_launch(void* const* d_in, const int* in_sizes, int n_in,
                              void* d_out, int out_size)
{
    const float* x           = (const float*)d_in[0];  // (T+1, 3, 64, 64)
    const int*   t_arr       = (const int*)  d_in[1];  // (T,)
    const float* alpha_ratio = (const float*)d_in[2];  // (T,1,1,1)
    const float* et_coeff    = (const float*)d_in[3];  // (T,1,1,1)
    const float* epc         = (const float*)d_in[4];  // (T,1,1,1)
    const float* conv_w      = (const float*)d_in[5];  // (3,3,3,3)
    const float* temb        = (const float*)d_in[6];  // (T, 3)
    float*       out         = (float*)d_out;

    cudaMemcpyToSymbolAsync(c_w, conv_w, 81 * sizeof(float), 0,
                            cudaMemcpyDeviceToDevice);

    dim3 gA(H_DIM / TILE_ROWS, T_STEPS), bA(256);      // (4, 1000)
    dim3 gB(PIX4 / 128, NSEG),           bB(128);      // (24, 50)
    dim3 gP(PIX / 256),                  bP(256);      // (48)
    dim3 gC(PIX4 / 128, NSEG),           bC(128);      // (24, 50)

    for (int it = 0; it < 3; it++) {
        const float* src = (it == 0) ? x : out;  // conv reads images 0..T-1
        conv_kernel<<<gA, bA>>>(src, temb, t_arr, et_coeff);
        psum_kernel<<<gB, bB>>>();
        prefix_kernel<<<gP, bP>>>();
        scan_combine_kernel<<<gC, bC>>>(out, x, alpha_ratio, epc);
    }
}

// round 17
// speedup vs baseline: 1.1164x; 1.1164x over previous
#include <cuda_runtime.h>
#include <cuda_fp16.h>

#define T_STEPS 1000
#define C_CH    3
#define H_DIM   64
#define W_DIM   64
#define HW      (H_DIM * W_DIM)       // 4096
#define HW4     (HW / 4)              // 1024
#define PIX     (C_CH * HW)           // 12288
#define PIX4    (PIX / 4)             // 3072
#define NSEG    50
#define SEGLEN  (T_STEPS / NSEG)      // 20
#define TILE_ROWS 16

__device__ __half g_E[(size_t)T_STEPS * PIX];     // ~24.5 MB scratch (fp16)
__device__ float  g_Psum[NSEG * PIX];             // ~2.5 MB
__device__ float  g_Ppre[NSEG * PIX];             // exclusive prefix of g_Psum
__constant__ float c_w[81];                       // conv weights (LDCU port)

// ---------------------------------------------------------------------------
// Kernel A (proven R7 body, fp16 E stores): 256 threads, one (16-row tile,
// image j). Thread = 1 row x 4 cols x 3 output channels (12 accumulators).
// ---------------------------------------------------------------------------
__global__ __launch_bounds__(256, 4) void conv_kernel(
    const float* __restrict__ src,       // images 0..T-1, (.., C, H, W)
    const float* __restrict__ temb,      // (T, 3)
    const int*   __restrict__ t_arr,     // (T,)
    const float* __restrict__ et_coeff)  // (T,)
{
    __shared__ float4 s_in4[3][18][18];  // [ci][row][quad]; quad q = cols 4q-4..4q-1

    const int j   = blockIdx.y;
    const int r0  = blockIdx.x * TILE_ROWS;
    const int tid = threadIdx.x;
    const int h   = tid >> 4;            // row 0..15
    const int k   = tid & 15;            // col-group 0..15 (cols 4k..4k+3)

    const float4* img4 = (const float4*)(src + (size_t)j * PIX);
    for (int l = tid; l < 3 * 18 * 18; l += 256) {
        int ci  = l / 324;
        int rem = l - ci * 324;
        int r   = rem / 18;
        int q   = rem - r * 18;
        int gh  = r0 + r - 1;
        float4 v = make_float4(0.f, 0.f, 0.f, 0.f);
        if (q >= 1 && q <= 16 && gh >= 0 && gh < H_DIM)
            v = img4[ci * HW4 + gh * 16 + (q - 1)];
        (&s_in4[0][0][0])[l] = v;
    }
    __syncthreads();

    const int   trev = __ldg(t_arr + j);
    const float ec   = __ldg(et_coeff + j);

    float acc[3][4];
#pragma unroll
    for (int c = 0; c < 3; c++) {
        const float tb = __ldg(temb + trev * 3 + c);
#pragma unroll
        for (int s = 0; s < 4; s++) acc[c][s] = tb;
    }

#pragma unroll 1
    for (int ci = 0; ci < 3; ci++) {
        float v[3][6];
#pragma unroll
        for (int r = 0; r < 3; r++) {
            float4 A = s_in4[ci][h + r][k];
            float4 B = s_in4[ci][h + r][k + 1];
            float4 C = s_in4[ci][h + r][k + 2];
            v[r][0] = A.w; v[r][1] = B.x; v[r][2] = B.y;
            v[r][3] = B.z; v[r][4] = B.w; v[r][5] = C.x;
        }
#pragma unroll
        for (int dh = 0; dh < 3; dh++)
#pragma unroll
            for (int dw = 0; dw < 3; dw++) {
                const int tap = ci * 9 + dh * 3 + dw;
                const float w0 = c_w[tap];
                const float w1 = c_w[27 + tap];
                const float w2 = c_w[54 + tap];
#pragma unroll
                for (int s = 0; s < 4; s++) {
                    const float xv = v[dh][dw + s];
                    acc[0][s] = fmaf(w0, xv, acc[0][s]);
                    acc[1][s] = fmaf(w1, xv, acc[1][s]);
                    acc[2][s] = fmaf(w2, xv, acc[2][s]);
                }
            }
    }

    __half* Ej = g_E + (size_t)j * PIX;
    const int gq = (r0 + h) * 16 + k;            // float4-group index in channel plane
#pragma unroll
    for (int c = 0; c < 3; c++) {
        union { uint2 u; __half2 h[2]; } pk;
        pk.h[0] = __floats2half2_rn(acc[c][0] * ec, acc[c][1] * ec);
        pk.h[1] = __floats2half2_rn(acc[c][2] * ec, acc[c][3] * ec);
        *(uint2*)(Ej + c * HW + gq * 4) = pk.u;  // STG.64
    }
}

// ---------------------------------------------------------------------------
// Kernel B: per-segment partial sums of E (fp16 loads, fp32 accumulate).
// ---------------------------------------------------------------------------
__global__ __launch_bounds__(128) void psum_kernel()
{
    const int p4  = blockIdx.x * 128 + threadIdx.x;   // < PIX4
    const int seg = blockIdx.y;
    const __half* base = g_E + (size_t)seg * SEGLEN * PIX + p4 * 4;

    // batch all loads first (MLP = SEGLEN)
    uint2 u[SEGLEN];
#pragma unroll
    for (int j = 0; j < SEGLEN; j++)
        u[j] = *(const uint2*)(base + (size_t)j * PIX);

    float4 s = make_float4(0.f, 0.f, 0.f, 0.f);
#pragma unroll
    for (int j = 0; j < SEGLEN; j++) {
        float2 f0 = __half22float2(*(const __half2*)&u[j].x);
        float2 f1 = __half22float2(*(const __half2*)&u[j].y);
        s.x += f0.x; s.y += f0.y; s.z += f1.x; s.w += f1.y;
    }
    ((float4*)g_Psum)[seg * PIX4 + p4] = s;
}

// ---------------------------------------------------------------------------
// Kernel B2: exclusive prefix of g_Psum (batched loads for MLP).
// ---------------------------------------------------------------------------
__global__ __launch_bounds__(256) void prefix_kernel()
{
    const int p = blockIdx.x * 256 + threadIdx.x;     // < PIX
    float run = 0.f;
#pragma unroll 1
    for (int sb = 0; sb < NSEG; sb += 10) {
        float v[10];
#pragma unroll
        for (int i = 0; i < 10; i++)
            v[i] = g_Psum[(sb + i) * PIX + p];
#pragma unroll
        for (int i = 0; i < 10; i++) {
            g_Ppre[(sb + i) * PIX + p] = run;
            run += v[i];
        }
    }
}

// ---------------------------------------------------------------------------
// Kernel C: scan + combine. Two-phase: ALL E loads issued up front (MLP=20),
// then the FADD chain + stores run from registers.
// ---------------------------------------------------------------------------
__global__ __launch_bounds__(128) void scan_combine_kernel(
    float*       __restrict__ dst,          // (T+1, C, H, W)
    const float* __restrict__ xT,           // first image of original x
    const float* __restrict__ alpha_ratio,  // (T,)
    const float* __restrict__ epc)          // (T,)
{
    const int seg = blockIdx.y;
    const int p4  = blockIdx.x * 128 + threadIdx.x;   // < PIX4
    const int t0  = seg * SEGLEN;

    // phase 1: batch all independent loads
    const __half* base = g_E + (size_t)t0 * PIX + p4 * 4;
    uint2 u[SEGLEN];
#pragma unroll
    for (int jj = 0; jj < SEGLEN; jj++)
        u[jj] = __ldcs((const uint2*)(base + (size_t)jj * PIX));

    float4 acc = ((const float4*)g_Ppre)[seg * PIX4 + p4];
    const float4 xv = ((const float4*)xT)[p4];
    if (seg == 0)
        ((float4*)dst)[p4] = xv;             // image 0 stays xT

    // phase 2: chain + emit from registers
#pragma unroll
    for (int jj = 0; jj < SEGLEN; jj++) {
        const int j = t0 + jj;
        float2 f0 = __half22float2(*(const __half2*)&u[jj].x);
        float2 f1 = __half22float2(*(const __half2*)&u[jj].y);
        acc.x += f0.x; acc.y += f0.y; acc.z += f1.x; acc.w += f1.y;
        const float ar = __ldg(alpha_ratio + j);
        const float ep = __ldg(epc + j);
        float4 o;
        o.x = fmaf(ar, xv.x, ep * acc.x);
        o.y = fmaf(ar, xv.y, ep * acc.y);
        o.z = fmaf(ar, xv.z, ep * acc.z);
        o.w = fmaf(ar, xv.w, ep * acc.w);
        ((float4*)dst)[(size_t)(j + 1) * PIX4 + p4] = o;
    }
}

extern "C" void kernel_launch(void* const* d_in, const int* in_sizes, int n_in,
                              void* d_out, int out_size)
{
    const float* x           = (const float*)d_in[0];  // (T+1, 3, 64, 64)
    const int*   t_arr       = (const int*)  d_in[1];  // (T,)
    const float* alpha_ratio = (const float*)d_in[2];  // (T,1,1,1)
    const float* et_coeff    = (const float*)d_in[3];  // (T,1,1,1)
    const float* epc         = (const float*)d_in[4];  // (T,1,1,1)
    const float* conv_w      = (const float*)d_in[5];  // (3,3,3,3)
    const float* temb        = (const float*)d_in[6];  // (T, 3)
    float*       out         = (float*)d_out;

    cudaMemcpyToSymbolAsync(c_w, conv_w, 81 * sizeof(float), 0,
                            cudaMemcpyDeviceToDevice);

    dim3 gA(H_DIM / TILE_ROWS, T_STEPS), bA(256);      // (4, 1000)
    dim3 gB(PIX4 / 128, NSEG),           bB(128);      // (24, 50)
    dim3 gP(PIX / 256),                  bP(256);      // (48)
    dim3 gC(PIX4 / 128, NSEG),           bC(128);      // (24, 50)

    for (int it = 0; it < 3; it++) {
        const float* src = (it == 0) ? x : out;  // conv reads images 0..T-1
        conv_kernel<<<gA, bA>>>(src, temb, t_arr, et_coeff);
        psum_kernel<<<gB, bB>>>();
        prefix_kernel<<<gP, bP>>>();
        scan_combine_kernel<<<gC, bC>>>(out, x, alpha_ratio, epc);
    }
}